// round 17
// baseline (speedup 1.0000x reference)
#include <cuda_runtime.h>
#include <cstdint>

#define BATCH 32768
#define TT 21
#define FIN 126
#define GG 32
#define NC 27

#define THREADS 128
#define WPB 4                  // warps per block
#define EPW 16                 // elements per warp (4 per octet-thread)
#define XSTR 132               // padded floats per staged row
#define ROWLEN (TT * FIN)      // 2646

// dynamic smem arena layout (bytes)
#define SM_XS    0
#define XS_BYTES (WPB * EPW * XSTR * 4)          // 33792
#define SM_WK    XS_BYTES                        // 33792, 128*8 ulonglong2 = 16384
#define SM_W2A   (SM_WK + 16384)                 // 50176, 1024
#define SM_W2B   (SM_W2A + 1024)                 // 51200, 1024
#define SM_H1    (SM_W2B + 1024)                 // 52224, WPB*16*10 ull = 5120
#define SM_H2    (SM_H1 + 5120)                  // 57344, 5120
#define SMEM_TOTAL (SM_H2 + 5120)                // 62464

typedef unsigned long long ull;

// ---------------- packed f32x2 helpers ----------------
__device__ __forceinline__ ull fma2(ull a, ull b, ull c) {
    ull d;
    asm("fma.rn.f32x2 %0, %1, %2, %3;" : "=l"(d) : "l"(a), "l"(b), "l"(c));
    return d;
}
__device__ __forceinline__ ull bcast2(float v) {
    ull d;
    asm("mov.b64 %0, {%1, %2};" : "=l"(d) : "f"(v), "f"(v));
    return d;
}
__device__ __forceinline__ ull pack2(float lo, float hi) {
    ull d;
    asm("mov.b64 %0, {%1, %2};" : "=l"(d) : "f"(lo), "f"(hi));
    return d;
}
__device__ __forceinline__ void unpack2(float& lo, float& hi, ull v) {
    asm("mov.b64 {%0, %1}, %2;" : "=f"(lo), "=f"(hi) : "l"(v));
}
__device__ __forceinline__ uint32_t smem_u32(const void* p) {
    uint32_t a;
    asm("{ .reg .u64 t; cvta.to.shared.u64 t, %1; cvt.u32.u64 %0, t; }" : "=r"(a) : "l"(p));
    return a;
}
__device__ __forceinline__ void cpa8(uint32_t saddr, const void* g) {
    asm volatile("cp.async.ca.shared.global [%0], [%1], 8;" :: "r"(saddr), "l"(g) : "memory");
}
#define CPA_COMMIT() asm volatile("cp.async.commit_group;" ::: "memory")
#define CPA_WAIT0()  asm volatile("cp.async.wait_group 0;" ::: "memory")

// Fast activations: MUFU-based, rel err ~1e-6 (threshold 1e-3)
__device__ __forceinline__ float sigm(float x) {
    return __fdividef(1.0f, 1.0f + __expf(-x));
}
__device__ __forceinline__ float tanhg(float x) {
    return __fdividef(2.0f, 1.0f + __expf(-2.0f * x)) - 1.0f;
}

// ---------------- Fused: projection + 2x LSTM + dense + softmax ----------------
// Octet handles FOUR elements; thread k owns unit k of all four.
// h exchange via DUPLICATED smem slots ({h,h} ull): 4 LDS.128 deliver 8
// broadcast-ready fma2 operands -> no SHFL, no bcast MOVs in the recurrence.
__global__ __launch_bounds__(THREADS)
void fused_lstm_kernel(const float* __restrict__ x,
                       const float* __restrict__ W1k, const float* __restrict__ b1,
                       const float* __restrict__ W1r,
                       const float* __restrict__ W2k, const float* __restrict__ W2r,
                       const float* __restrict__ b2,
                       const float* __restrict__ Wd, const float* __restrict__ bd,
                       float* __restrict__ out) {
    extern __shared__ __align__(16) char sm[];
    float* xs = (float*)(sm + SM_XS);                       // WPB*EPW*XSTR floats
    ulonglong2* sWk = (ulonglong2*)(sm + SM_WK);            // 128*8, cols 126/127 zero
    ulonglong2* sw2a = (ulonglong2*)(sm + SM_W2A);          // W2k [j*8+k]
    ulonglong2* sw2b = (ulonglong2*)(sm + SM_W2B);          // W2r [j*8+k]

    int tid = threadIdx.x;

    for (int i = tid; i < 128 * 8; i += THREADS) {
        int f = i >> 3, kk = i & 7;
        if (f < FIN) {
            const float* w = W1k + f * GG;
            sWk[i] = make_ulonglong2(pack2(w[kk], w[8 + kk]),
                                     pack2(w[16 + kk], w[24 + kk]));
        } else {
            sWk[i] = make_ulonglong2(0ull, 0ull);
        }
    }
    for (int i = tid; i < 64; i += THREADS) {
        int j = i >> 3, kk = i & 7;
        const float* pa = W2k + j * GG;
        const float* pb = W2r + j * GG;
        sw2a[i] = make_ulonglong2(pack2(pa[kk], pa[8 + kk]), pack2(pa[16 + kk], pa[24 + kk]));
        sw2b[i] = make_ulonglong2(pack2(pb[kk], pb[8 + kk]), pack2(pb[16 + kk], pb[24 + kk]));
    }
    __syncthreads();

    int warp = tid >> 5, lane = tid & 31;
    int k = lane & 7;
    int oct = lane >> 3;
    int ebase = blockIdx.x * (WPB * EPW) + warp * EPW;

    float* xsw = xs + warp * (EPW * XSTR);
    const uint32_t slab = smem_u32(xsw);

    // per-warp duplicated-h arenas: 16 elements x 10 ull (80B, 16B-aligned rows)
    ull* h1w = (ull*)(sm + SM_H1) + warp * 160;
    ull* h2w = (ull*)(sm + SM_H2) + warp * 160;

    // staging: 32 transfers i: row = i>>1 (0..15), 8B chunk index = (i&1)*32 + lane
    bool lastw = (blockIdx.x == gridDim.x - 1) && (warp == WPB - 1);
    const char* xgbase = (const char*)(x + (size_t)ebase * ROWLEN) + 8 * lane;
    const uint32_t sbase_lane = slab + 8 * lane;

    // Per-unit weights/biases in registers
    ull w1if[8], w1go[8];
#pragma unroll
    for (int j = 0; j < 8; ++j) {
        const float* r1 = W1r + j * GG;
        w1if[j] = pack2(r1[k], r1[8 + k]);
        w1go[j] = pack2(r1[16 + k], r1[24 + k]);
    }
    ull b1if = pack2(b1[k], b1[8 + k]);
    ull b1go = pack2(b1[16 + k], b1[24 + k]);
    ull b2if = pack2(b2[k], b2[8 + k]);
    ull b2go = pack2(b2[16 + k], b2[24 + k]);

    float c1[4] = {0.f, 0.f, 0.f, 0.f}, c2[4] = {0.f, 0.f, 0.f, 0.f};

    // zero-init h slots (thread covers j=k of its 4 elements, both layers)
#pragma unroll
    for (int r = 0; r < 4; ++r) {
        h1w[(4 * r + oct) * 10 + k] = 0ull;
        h2w[(4 * r + oct) * 10 + k] = 0ull;
    }

    // ---- stage t = 0 ----
    {
#pragma unroll
        for (int i = 0; i < 32; ++i) {
            int row = i >> 1;
            size_t goff = (size_t)row * (ROWLEN * 4) + (size_t)(i & 1) * 256;
            uint32_t soff = row * (XSTR * 4) + (i & 1) * 256;
            cpa8(sbase_lane + soff, xgbase + goff);
        }
        CPA_COMMIT();
        CPA_WAIT0();
        __syncwarp();
    }

    // element of (oct, r) = ebase + 4r + oct; slab row = 4r + oct
    const float* xr0 = xsw + (0 + oct) * XSTR;
    const float* xr1 = xsw + (4 + oct) * XSTR;
    const float* xr2 = xsw + (8 + oct) * XSTR;
    const float* xr3 = xsw + (12 + oct) * XSTR;

    for (int t = 0; t < TT; ++t) {
        // ---- layer 1 projection: 128 padded cols, 4 elements ----
        ull zif[4], zgo[4];
#pragma unroll
        for (int r = 0; r < 4; ++r) { zif[r] = b1if; zgo[r] = b1go; }

#pragma unroll 4
        for (int p = 0; p < 32; ++p) {
            float4 v0 = *(const float4*)(xr0 + 4 * p);
            float4 v1 = *(const float4*)(xr1 + 4 * p);
            float4 v2 = *(const float4*)(xr2 + 4 * p);
            float4 v3 = *(const float4*)(xr3 + 4 * p);
            ulonglong2 w0 = sWk[(4 * p + 0) * 8 + k];
            ulonglong2 w1 = sWk[(4 * p + 1) * 8 + k];
            ulonglong2 w2 = sWk[(4 * p + 2) * 8 + k];
            ulonglong2 w3 = sWk[(4 * p + 3) * 8 + k];
            ull b;
            b = bcast2(v0.x); zif[0] = fma2(b, w0.x, zif[0]); zgo[0] = fma2(b, w0.y, zgo[0]);
            b = bcast2(v1.x); zif[1] = fma2(b, w0.x, zif[1]); zgo[1] = fma2(b, w0.y, zgo[1]);
            b = bcast2(v2.x); zif[2] = fma2(b, w0.x, zif[2]); zgo[2] = fma2(b, w0.y, zgo[2]);
            b = bcast2(v3.x); zif[3] = fma2(b, w0.x, zif[3]); zgo[3] = fma2(b, w0.y, zgo[3]);
            b = bcast2(v0.y); zif[0] = fma2(b, w1.x, zif[0]); zgo[0] = fma2(b, w1.y, zgo[0]);
            b = bcast2(v1.y); zif[1] = fma2(b, w1.x, zif[1]); zgo[1] = fma2(b, w1.y, zgo[1]);
            b = bcast2(v2.y); zif[2] = fma2(b, w1.x, zif[2]); zgo[2] = fma2(b, w1.y, zgo[2]);
            b = bcast2(v3.y); zif[3] = fma2(b, w1.x, zif[3]); zgo[3] = fma2(b, w1.y, zgo[3]);
            b = bcast2(v0.z); zif[0] = fma2(b, w2.x, zif[0]); zgo[0] = fma2(b, w2.y, zgo[0]);
            b = bcast2(v1.z); zif[1] = fma2(b, w2.x, zif[1]); zgo[1] = fma2(b, w2.y, zgo[1]);
            b = bcast2(v2.z); zif[2] = fma2(b, w2.x, zif[2]); zgo[2] = fma2(b, w2.y, zgo[2]);
            b = bcast2(v3.z); zif[3] = fma2(b, w2.x, zif[3]); zgo[3] = fma2(b, w2.y, zgo[3]);
            b = bcast2(v0.w); zif[0] = fma2(b, w3.x, zif[0]); zgo[0] = fma2(b, w3.y, zgo[0]);
            b = bcast2(v1.w); zif[1] = fma2(b, w3.x, zif[1]); zgo[1] = fma2(b, w3.y, zgo[1]);
            b = bcast2(v2.w); zif[2] = fma2(b, w3.x, zif[2]); zgo[2] = fma2(b, w3.y, zgo[2]);
            b = bcast2(v3.w); zif[3] = fma2(b, w3.x, zif[3]); zgo[3] = fma2(b, w3.y, zgo[3]);
        }

        // ---- stage x_{t+1} (async; slab reads for t done; warp-lockstep => WAR safe) ----
        if (t < TT - 1) {
            const char* xgt = xgbase + (size_t)(t + 1) * (FIN * 4);
#pragma unroll
            for (int i = 0; i < 32; ++i) {
                int row = i >> 1;
                size_t goff = (size_t)row * (ROWLEN * 4) + (size_t)(i & 1) * 256;
                uint32_t soff = row * (XSTR * 4) + (i & 1) * 256;
                if (i == 31 && lane == 31 && t + 1 == TT - 1 && lastw)
                    continue;   // last 8B of x would be OOB; cols 126/127 have zero weights
                cpa8(sbase_lane + soff, xgt + goff);
            }
            CPA_COMMIT();
        }

        // ---- layer 1 recurrent: h1_old from dup smem (4 LDS.128 per r, no shfl) ----
#pragma unroll
        for (int r = 0; r < 4; ++r) {
            const ulonglong2* hp = (const ulonglong2*)(h1w + (4 * r + oct) * 10);
            ulonglong2 p0 = hp[0], p1 = hp[1], p2 = hp[2], p3 = hp[3];
            zif[r] = fma2(p0.x, w1if[0], zif[r]); zgo[r] = fma2(p0.x, w1go[0], zgo[r]);
            zif[r] = fma2(p0.y, w1if[1], zif[r]); zgo[r] = fma2(p0.y, w1go[1], zgo[r]);
            zif[r] = fma2(p1.x, w1if[2], zif[r]); zgo[r] = fma2(p1.x, w1go[2], zgo[r]);
            zif[r] = fma2(p1.y, w1if[3], zif[r]); zgo[r] = fma2(p1.y, w1go[3], zgo[r]);
            zif[r] = fma2(p2.x, w1if[4], zif[r]); zgo[r] = fma2(p2.x, w1go[4], zgo[r]);
            zif[r] = fma2(p2.y, w1if[5], zif[r]); zgo[r] = fma2(p2.y, w1go[5], zgo[r]);
            zif[r] = fma2(p3.x, w1if[6], zif[r]); zgo[r] = fma2(p3.x, w1go[6], zgo[r]);
            zif[r] = fma2(p3.y, w1if[7], zif[r]); zgo[r] = fma2(p3.y, w1go[7], zgo[r]);
        }
        __syncwarp();   // all h1_old reads done before overwrite
#pragma unroll
        for (int r = 0; r < 4; ++r) {
            float zi, zf, zg, zo;
            unpack2(zi, zf, zif[r]);
            unpack2(zg, zo, zgo[r]);
            c1[r] = sigm(zf) * c1[r] + sigm(zi) * tanhg(zg);
            float h1v = sigm(zo) * tanhg(c1[r]);
            h1w[(4 * r + oct) * 10 + k] = pack2(h1v, h1v);
        }
        __syncwarp();   // h1_new visible

        // ---- layer 2: h1_new + h2_old from dup smem ----
#pragma unroll
        for (int r = 0; r < 4; ++r) { zif[r] = b2if; zgo[r] = b2go; }
#pragma unroll
        for (int r = 0; r < 4; ++r) {
            const ulonglong2* ap = (const ulonglong2*)(h1w + (4 * r + oct) * 10);
            const ulonglong2* bp = (const ulonglong2*)(h2w + (4 * r + oct) * 10);
            ulonglong2 a0 = ap[0], a1 = ap[1], a2 = ap[2], a3 = ap[3];
            ulonglong2 q0 = bp[0], q1 = bp[1], q2 = bp[2], q3 = bp[3];
            ulonglong2 wa0 = sw2a[0 * 8 + k], wa1 = sw2a[1 * 8 + k];
            ulonglong2 wa2 = sw2a[2 * 8 + k], wa3 = sw2a[3 * 8 + k];
            ulonglong2 wa4 = sw2a[4 * 8 + k], wa5 = sw2a[5 * 8 + k];
            ulonglong2 wa6 = sw2a[6 * 8 + k], wa7 = sw2a[7 * 8 + k];
            ulonglong2 wb0 = sw2b[0 * 8 + k], wb1 = sw2b[1 * 8 + k];
            ulonglong2 wb2 = sw2b[2 * 8 + k], wb3 = sw2b[3 * 8 + k];
            ulonglong2 wb4 = sw2b[4 * 8 + k], wb5 = sw2b[5 * 8 + k];
            ulonglong2 wb6 = sw2b[6 * 8 + k], wb7 = sw2b[7 * 8 + k];
            zif[r] = fma2(a0.x, wa0.x, zif[r]); zgo[r] = fma2(a0.x, wa0.y, zgo[r]);
            zif[r] = fma2(q0.x, wb0.x, zif[r]); zgo[r] = fma2(q0.x, wb0.y, zgo[r]);
            zif[r] = fma2(a0.y, wa1.x, zif[r]); zgo[r] = fma2(a0.y, wa1.y, zgo[r]);
            zif[r] = fma2(q0.y, wb1.x, zif[r]); zgo[r] = fma2(q0.y, wb1.y, zgo[r]);
            zif[r] = fma2(a1.x, wa2.x, zif[r]); zgo[r] = fma2(a1.x, wa2.y, zgo[r]);
            zif[r] = fma2(q1.x, wb2.x, zif[r]); zgo[r] = fma2(q1.x, wb2.y, zgo[r]);
            zif[r] = fma2(a1.y, wa3.x, zif[r]); zgo[r] = fma2(a1.y, wa3.y, zgo[r]);
            zif[r] = fma2(q1.y, wb3.x, zif[r]); zgo[r] = fma2(q1.y, wb3.y, zgo[r]);
            zif[r] = fma2(a2.x, wa4.x, zif[r]); zgo[r] = fma2(a2.x, wa4.y, zgo[r]);
            zif[r] = fma2(q2.x, wb4.x, zif[r]); zgo[r] = fma2(q2.x, wb4.y, zgo[r]);
            zif[r] = fma2(a2.y, wa5.x, zif[r]); zgo[r] = fma2(a2.y, wa5.y, zgo[r]);
            zif[r] = fma2(q2.y, wb5.x, zif[r]); zgo[r] = fma2(q2.y, wb5.y, zgo[r]);
            zif[r] = fma2(a3.x, wa6.x, zif[r]); zgo[r] = fma2(a3.x, wa6.y, zgo[r]);
            zif[r] = fma2(q3.x, wb6.x, zif[r]); zgo[r] = fma2(q3.x, wb6.y, zgo[r]);
            zif[r] = fma2(a3.y, wa7.x, zif[r]); zgo[r] = fma2(a3.y, wa7.y, zgo[r]);
            zif[r] = fma2(q3.y, wb7.x, zif[r]); zgo[r] = fma2(q3.y, wb7.y, zgo[r]);
        }
        __syncwarp();   // all h2_old reads done before overwrite
#pragma unroll
        for (int r = 0; r < 4; ++r) {
            float zi, zf, zg, zo;
            unpack2(zi, zf, zif[r]);
            unpack2(zg, zo, zgo[r]);
            c2[r] = sigm(zf) * c2[r] + sigm(zi) * tanhg(zg);
            float h2v = sigm(zo) * tanhg(c2[r]);
            h2w[(4 * r + oct) * 10 + k] = pack2(h2v, h2v);
        }

        // ---- ensure staged x_{t+1} landed (also publishes h2_new) ----
        if (t < TT - 1) {
            CPA_WAIT0();
        }
        __syncwarp();
    }

    // ---- dense + softmax per element (h2 read from dup smem) ----
#pragma unroll
    for (int r = 0; r < 4; ++r) {
        const ulonglong2* bp = (const ulonglong2*)(h2w + (4 * r + oct) * 10);
        float h2f[8];
#pragma unroll
        for (int i = 0; i < 4; ++i) {
            ulonglong2 q = bp[i];
            float lo, hi;
            unpack2(lo, hi, q.x); h2f[2 * i] = lo;
            unpack2(lo, hi, q.y); h2f[2 * i + 1] = lo;
        }

        float lg[4];
#pragma unroll
        for (int q = 0; q < 4; ++q) {
            int m = q * 8 + k;
            float acc = (m < NC) ? bd[m] : -1e30f;
            if (m < NC) {
#pragma unroll
                for (int j = 0; j < 8; ++j) acc += h2f[j] * Wd[j * NC + m];
            }
            lg[q] = acc;
        }
        float mx = fmaxf(fmaxf(lg[0], lg[1]), fmaxf(lg[2], lg[3]));
#pragma unroll
        for (int off = 4; off >= 1; off >>= 1)
            mx = fmaxf(mx, __shfl_xor_sync(0xffffffffu, mx, off));
        float s = 0.f;
#pragma unroll
        for (int q = 0; q < 4; ++q) {
            float v = (q * 8 + k < NC) ? __expf(lg[q] - mx) : 0.f;
            lg[q] = v;
            s += v;
        }
#pragma unroll
        for (int off = 4; off >= 1; off >>= 1)
            s += __shfl_xor_sync(0xffffffffu, s, off);
        float inv = __fdividef(1.0f, s);
        int e = ebase + 4 * r + oct;
        float* op = out + (size_t)e * NC;
#pragma unroll
        for (int q = 0; q < 4; ++q) {
            int m = q * 8 + k;
            if (m < NC) op[m] = lg[q] * inv;
        }
    }
}

// ---------------- launch ----------------
extern "C" void kernel_launch(void* const* d_in, const int* in_sizes, int n_in,
                              void* d_out, int out_size) {
    const float* x   = (const float*)d_in[0];
    const float* W1k = (const float*)d_in[1];
    const float* W1r = (const float*)d_in[2];
    const float* b1  = (const float*)d_in[3];
    const float* W2k = (const float*)d_in[4];
    const float* W2r = (const float*)d_in[5];
    const float* b2  = (const float*)d_in[6];
    const float* Wd  = (const float*)d_in[7];
    const float* bd  = (const float*)d_in[8];
    float* out = (float*)d_out;

    cudaFuncSetAttribute(fused_lstm_kernel,
                         cudaFuncAttributeMaxDynamicSharedMemorySize, SMEM_TOTAL);
    fused_lstm_kernel<<<BATCH / (WPB * EPW), THREADS, SMEM_TOTAL>>>(
        x, W1k, b1, W1r, W2k, W2r, b2, Wd, bd, out);
}